// round 6
// baseline (speedup 1.0000x reference)
#include <cuda_runtime.h>
#include <cuda_bf16.h>
#include <math.h>
#include <stdint.h>

#define Nn 4096
#define Ff 512
#define Dd 64
#define Hh 8
#define HD 512   // Hh*Dd
#define Cc 40
#define C2 64    // padded class dim
#define MAXDEG 128

// ---------------- scratch (static device globals; no allocation) -------------
__device__ int   g_deg[Nn];
__device__ int   g_nbr[Nn * MAXDEG];
__device__ float g_h[(size_t)Nn * HD];     // layer1 features, [n][h*D+d]
__device__ float g_si[Hh * Nn];
__device__ float g_sj[Hh * Nn];
__device__ float g_x2[(size_t)Nn * HD];
__device__ float g_h2p[(size_t)Nn * C2];   // padded h2 (cols 40..63 are 0)
__device__ float g_s2i[Nn];
__device__ float g_s2j[Nn];
__device__ int   g_flag2[128];             // per-block ready flags (fused2)

// ---------------- helpers ----------------------------------------------------
__device__ __forceinline__ uint32_t f2tf(float x) {
    uint32_t r;
    asm("cvt.rna.tf32.f32 %0, %1;" : "=r"(r) : "f"(x));
    return r;
}
__device__ __forceinline__ void cp16(uint32_t dst_smem, const void* src) {
    asm volatile("cp.async.cg.shared.global [%0], [%1], 16;\n"
                 :: "r"(dst_smem), "l"(src) : "memory");
}
__device__ __forceinline__ void cp_commit() {
    asm volatile("cp.async.commit_group;\n" ::: "memory");
}
__device__ __forceinline__ void cp_wait1() {
    asm volatile("cp.async.wait_group 1;\n" ::: "memory");
}
__device__ __forceinline__ void cp_wait0() {
    asm volatile("cp.async.wait_group 0;\n" ::: "memory");
}
__device__ __forceinline__ void mma_tf32(float* c, uint32_t a0, uint32_t a1,
                                         uint32_t a2, uint32_t a3,
                                         uint32_t b0, uint32_t b1) {
    asm volatile(
        "mma.sync.aligned.m16n8k8.row.col.f32.tf32.tf32.f32 "
        "{%0,%1,%2,%3}, {%4,%5,%6,%7}, {%8,%9}, {%0,%1,%2,%3};"
        : "+f"(c[0]), "+f"(c[1]), "+f"(c[2]), "+f"(c[3])
        : "r"(a0), "r"(a1), "r"(a2), "r"(a3), "r"(b0), "r"(b1));
}

__device__ __forceinline__ int detect_mode(const unsigned char* adj) {
    if (adj[(size_t)Nn + 1] == 1) return 0;                               // u8
    if (((const uint16_t*)adj)[(size_t)Nn + 1] == 0x3F80u) return 3;      // bf16
    uint32_t v32 = ((const uint32_t*)adj)[(size_t)Nn + 1];
    if (v32 == 0x3F800000u) return 2;                                     // f32
    if (((const uint64_t*)adj)[(size_t)Nn + 1] == 0x3FF0000000000000ull) return 4; // f64
    return 1;                                                             // i32
}
__device__ __forceinline__ unsigned nz4(unsigned w) {
    unsigned c = 0;
    if (w & 0x000000FFu) c |= 1u;
    if (w & 0x0000FF00u) c |= 2u;
    if (w & 0x00FF0000u) c |= 4u;
    if (w & 0xFF000000u) c |= 8u;
    return c;
}
__device__ __forceinline__ int emit_mask(int row, int cnt, unsigned msk,
                                         int j0, int lane) {
    const unsigned FULL = 0xffffffffu;
    int c = __popc(msk);
    int pref = c;
    #pragma unroll
    for (int o = 1; o < 32; o <<= 1) {
        int n = __shfl_up_sync(FULL, pref, o);
        if (lane >= o) pref += n;
    }
    int pos = cnt + pref - c;
    while (msk) {
        int b = __ffs(msk) - 1;
        msk &= msk - 1;
        if (pos < MAXDEG) g_nbr[row * MAXDEG + pos] = j0 + b;
        pos++;
    }
    return cnt + __shfl_sync(FULL, pref, 31);
}

// ---------------- adjacency build (device fn; 1 warp per row) ----------------
__device__ void build_rows(const unsigned char* adj, int rb) {
    int row  = rb * 8 + (threadIdx.x >> 5);
    int lane = threadIdx.x & 31;
    int mode = detect_mode(adj);
    int cnt = 0;

    if (mode == 0) {
        const uint4* r = (const uint4*)(adj + (size_t)row * Nn);
        #pragma unroll
        for (int it = 0; it < Nn / 512; it++) {
            uint4 v = r[it * 32 + lane];
            unsigned msk = nz4(v.x) | (nz4(v.y) << 4) | (nz4(v.z) << 8) | (nz4(v.w) << 12);
            cnt = emit_mask(row, cnt, msk, it * 512 + lane * 16, lane);
        }
    } else if (mode == 1 || mode == 2) {
        const uint4* r = (const uint4*)adj + (size_t)row * (Nn / 4);
        for (int it = 0; it < Nn / 128; it++) {
            uint4 v = r[it * 32 + lane];
            unsigned msk = (v.x ? 1u : 0u) | (v.y ? 2u : 0u) | (v.z ? 4u : 0u) | (v.w ? 8u : 0u);
            cnt = emit_mask(row, cnt, msk, it * 128 + lane * 4, lane);
        }
    } else if (mode == 3) {
        const uint4* r = (const uint4*)adj + (size_t)row * (Nn / 8);
        for (int it = 0; it < Nn / 256; it++) {
            uint4 v = r[it * 32 + lane];
            unsigned msk = 0;
            unsigned w[4] = {v.x, v.y, v.z, v.w};
            #pragma unroll
            for (int q = 0; q < 4; q++) {
                if (w[q] & 0x0000FFFFu) msk |= 1u << (2 * q);
                if (w[q] & 0xFFFF0000u) msk |= 2u << (2 * q);
            }
            cnt = emit_mask(row, cnt, msk, it * 256 + lane * 8, lane);
        }
    } else {
        const double* rd = (const double*)adj + (size_t)row * Nn;
        const unsigned FULL = 0xffffffffu;
        for (int base = 0; base < Nn; base += 32) {
            int j = base + lane;
            bool edge = rd[j] != 0.0;
            unsigned m = __ballot_sync(FULL, edge);
            if (edge) {
                int pos = cnt + __popc(m & ((1u << lane) - 1u));
                if (pos < MAXDEG) g_nbr[row * MAXDEG + pos] = j;
            }
            cnt += __popc(m);
        }
    }
    if (lane == 0) g_deg[row] = (cnt < MAXDEG) ? cnt : MAXDEG;
}

// ------- TF32 GEMM tile (3xTF32, cp.async double-buffered, fused row dots) ---
// C[row0:row0+BM, col0:col0+64] = A[.,512] @ B; warps 2(M) x 4(N).
// B rows are BCH*4 floats (64 for W1 slice, 40 for W2 -> cols padded to 0).
// Epilogue: si_out[row] = C_row . avd (cols < AVALID), sj_out likewise w/ avs.
template <int BM, int BCH, int AVALID>
__device__ __forceinline__ void gemm_tile(
    const float* __restrict__ A, const float* __restrict__ Bp,
    float* __restrict__ Cm, int Nc, int row0, int col0,
    const float* __restrict__ avs, const float* __restrict__ avd,
    float* __restrict__ si_out, float* __restrict__ sj_out, float* sm)
{
    constexpr int K = 512;
    constexpr int WM = BM / 2;
    constexpr int MF = WM / 16;
    constexpr int NF = 2;
    constexpr int BROW = BCH * 4;

    float* As_  = sm;                       // [2][BM][36]
    float* Bs_  = sm + 2 * BM * 36;         // [2][32][72]
    float* s_si = Bs_ + 2 * 32 * 72;        // [4][BM]
    float* s_sj = s_si + 4 * BM;            // [4][BM]
    uint32_t smb = (uint32_t)__cvta_generic_to_shared(sm);
    uint32_t asb = smb;
    uint32_t bsb = smb + 2 * BM * 36 * 4;

    int t = threadIdx.x, lane = t & 31, wid = t >> 5;
    int warpM = wid & 1, warpN = wid >> 1;
    int gId = lane >> 2, tig = lane & 3;

    if (BCH < 16) {   // zero-pad Bs cols [BROW,72) for both stages
        for (int id = t; id < 64 * (72 - BROW); id += 256) {
            int r = id / (72 - BROW), c = id % (72 - BROW);
            Bs_[r * 72 + BROW + c] = 0.f;
        }
    }

    float acc[MF][NF][4];
    #pragma unroll
    for (int i = 0; i < MF; i++)
        #pragma unroll
        for (int j = 0; j < NF; j++)
            #pragma unroll
            for (int q = 0; q < 4; q++) acc[i][j][q] = 0.f;

    auto issue = [&](int stage, int k0) {
        #pragma unroll
        for (int it = 0; it < BM * 8 / 256; it++) {
            int id = t + it * 256;
            int r = id >> 3, c = id & 7;
            cp16(asb + ((stage * BM + r) * 36 + c * 4) * 4,
                 A + (size_t)(row0 + r) * K + k0 + c * 4);
        }
        constexpr int TOT = 32 * BCH;
        #pragma unroll
        for (int it = 0; it < (TOT + 255) / 256; it++) {
            int id = t + it * 256;
            if (id < TOT) {
                int r = id / BCH, c = id % BCH;
                cp16(bsb + ((stage * 32 + r) * 72 + c * 4) * 4,
                     Bp + (size_t)(k0 + r) * BROW + c * 4);
            }
        }
        cp_commit();
    };

    issue(0, 0);
    for (int kt = 0; kt < K / 32; kt++) {
        int cur = kt & 1;
        if (kt + 1 < K / 32) { issue(cur ^ 1, (kt + 1) * 32); cp_wait1(); }
        else cp_wait0();
        __syncthreads();

        const float* Asc = As_ + cur * BM * 36;
        const float* Bsc = Bs_ + cur * 32 * 72;
        #pragma unroll
        for (int ks = 0; ks < 4; ks++) {
            int kk = ks * 8;
            uint32_t ah[MF][4], al[MF][4];
            #pragma unroll
            for (int mf = 0; mf < MF; mf++) {
                int m0 = warpM * WM + mf * 16 + gId;
                float f0 = Asc[m0 * 36 + kk + tig];
                float f1 = Asc[(m0 + 8) * 36 + kk + tig];
                float f2 = Asc[m0 * 36 + kk + tig + 4];
                float f3 = Asc[(m0 + 8) * 36 + kk + tig + 4];
                ah[mf][0] = f2tf(f0); al[mf][0] = f2tf(f0 - __uint_as_float(ah[mf][0]));
                ah[mf][1] = f2tf(f1); al[mf][1] = f2tf(f1 - __uint_as_float(ah[mf][1]));
                ah[mf][2] = f2tf(f2); al[mf][2] = f2tf(f2 - __uint_as_float(ah[mf][2]));
                ah[mf][3] = f2tf(f3); al[mf][3] = f2tf(f3 - __uint_as_float(ah[mf][3]));
            }
            uint32_t bh[NF][2], bl[NF][2];
            #pragma unroll
            for (int nf = 0; nf < NF; nf++) {
                int n0 = warpN * 16 + nf * 8 + gId;
                float g0 = Bsc[(kk + tig) * 72 + n0];
                float g1 = Bsc[(kk + tig + 4) * 72 + n0];
                bh[nf][0] = f2tf(g0); bl[nf][0] = f2tf(g0 - __uint_as_float(bh[nf][0]));
                bh[nf][1] = f2tf(g1); bl[nf][1] = f2tf(g1 - __uint_as_float(bh[nf][1]));
            }
            #pragma unroll
            for (int mf = 0; mf < MF; mf++)
                #pragma unroll
                for (int nf = 0; nf < NF; nf++) {
                    mma_tf32(acc[mf][nf], ah[mf][0], ah[mf][1], ah[mf][2], ah[mf][3],
                             bl[nf][0], bl[nf][1]);
                    mma_tf32(acc[mf][nf], al[mf][0], al[mf][1], al[mf][2], al[mf][3],
                             bh[nf][0], bh[nf][1]);
                    mma_tf32(acc[mf][nf], ah[mf][0], ah[mf][1], ah[mf][2], ah[mf][3],
                             bh[nf][0], bh[nf][1]);
                }
        }
        __syncthreads();
    }

    // ---- C store ----
    #pragma unroll
    for (int mf = 0; mf < MF; mf++) {
        int r0 = row0 + warpM * WM + mf * 16 + gId;
        #pragma unroll
        for (int nf = 0; nf < NF; nf++) {
            int c0 = col0 + warpN * 16 + nf * 8 + tig * 2;
            *(float2*)&Cm[(size_t)r0 * Nc + c0] = make_float2(acc[mf][nf][0], acc[mf][nf][1]);
            *(float2*)&Cm[(size_t)(r0 + 8) * Nc + c0] = make_float2(acc[mf][nf][2], acc[mf][nf][3]);
        }
    }

    // ---- fused row dots ----
    const unsigned FULL = 0xffffffffu;
    float advals[NF][2], asvals[NF][2];
    #pragma unroll
    for (int nf = 0; nf < NF; nf++) {
        int c = warpN * 16 + nf * 8 + tig * 2;
        advals[nf][0] = (c < AVALID) ? avd[c] : 0.f;
        asvals[nf][0] = (c < AVALID) ? avs[c] : 0.f;
        advals[nf][1] = (c + 1 < AVALID) ? avd[c + 1] : 0.f;
        asvals[nf][1] = (c + 1 < AVALID) ? avs[c + 1] : 0.f;
    }
    #pragma unroll
    for (int mf = 0; mf < MF; mf++) {
        float rAi = 0.f, rAj = 0.f, rBi = 0.f, rBj = 0.f;
        #pragma unroll
        for (int nf = 0; nf < NF; nf++) {
            rAi += acc[mf][nf][0] * advals[nf][0] + acc[mf][nf][1] * advals[nf][1];
            rAj += acc[mf][nf][0] * asvals[nf][0] + acc[mf][nf][1] * asvals[nf][1];
            rBi += acc[mf][nf][2] * advals[nf][0] + acc[mf][nf][3] * advals[nf][1];
            rBj += acc[mf][nf][2] * asvals[nf][0] + acc[mf][nf][3] * asvals[nf][1];
        }
        #pragma unroll
        for (int o = 1; o <= 2; o <<= 1) {
            rAi += __shfl_xor_sync(FULL, rAi, o);
            rAj += __shfl_xor_sync(FULL, rAj, o);
            rBi += __shfl_xor_sync(FULL, rBi, o);
            rBj += __shfl_xor_sync(FULL, rBj, o);
        }
        if (tig == 0) {
            int r = warpM * WM + mf * 16 + gId;
            s_si[warpN * BM + r] = rAi;
            s_sj[warpN * BM + r] = rAj;
            s_si[warpN * BM + r + 8] = rBi;
            s_sj[warpN * BM + r + 8] = rBj;
        }
    }
    __syncthreads();
    if (t < BM) {
        si_out[row0 + t] = s_si[t] + s_si[BM + t] + s_si[2 * BM + t] + s_si[3 * BM + t];
        sj_out[row0 + t] = s_sj[t] + s_sj[BM + t] + s_sj[2 * BM + t] + s_sj[3 * BM + t];
    }
}

// ---------------- launch 1: build ∪ GEMM1 (role-split blocks) ----------------
__global__ __launch_bounds__(256) void k_fused1(
    const float* __restrict__ x, const unsigned char* __restrict__ adj,
    const float* __restrict__ W1,
    const float* __restrict__ a1_src, const float* __restrict__ a1_dst)
{
    extern __shared__ float sm[];
    int bid = blockIdx.x;
    if (bid < 512) {
        int head = bid & 7, rb = bid >> 3;
        gemm_tile<64, 16, 64>(x, W1 + (size_t)head * Ff * Dd, g_h, HD,
                              rb * 64, head * 64,
                              a1_src + head * Dd, a1_dst + head * Dd,
                              g_si + head * Nn, g_sj + head * Nn, sm);
    } else {
        build_rows(adj, bid - 512);
    }
}

// ---------------- launch 2: layer-1 sparse attention + aggregate + ELU -------
__global__ __launch_bounds__(256) void k_layer1() {
    __shared__ int   nbr_sh[MAXDEG];
    __shared__ float w_sh[Hh][MAXDEG];
    int i = blockIdx.x;
    int deg = g_deg[i];
    int t = threadIdx.x, lane = t & 31, wid = t >> 5;
    if (i == 0 && t < 128) g_flag2[t] = 0;   // reset fused2 flags each call
    for (int jj = t; jj < deg; jj += 256) nbr_sh[jj] = g_nbr[i * MAXDEG + jj];
    __syncthreads();

    {
        int h = wid;
        float sii = g_si[h * Nn + i];
        float ev[4];
        float m = -1e30f;
        #pragma unroll
        for (int it = 0; it < 4; it++) {
            int jj = it * 32 + lane;
            float e = -1e30f;
            if (jj < deg) {
                float xx = sii + g_sj[h * Nn + nbr_sh[jj]];
                e = (xx >= 0.f) ? xx : 0.2f * xx;
            }
            ev[it] = e;
            m = fmaxf(m, e);
        }
        #pragma unroll
        for (int o = 16; o; o >>= 1) m = fmaxf(m, __shfl_xor_sync(0xffffffffu, m, o));
        float s = 0.f;
        #pragma unroll
        for (int it = 0; it < 4; it++) {
            int jj = it * 32 + lane;
            float w = (jj < deg) ? expf(ev[it] - m) : 0.f;
            ev[it] = w;
            s += w;
        }
        #pragma unroll
        for (int o = 16; o; o >>= 1) s += __shfl_xor_sync(0xffffffffu, s, o);
        float inv = 1.f / s;
        #pragma unroll
        for (int it = 0; it < 4; it++) {
            int jj = it * 32 + lane;
            if (jj < deg) w_sh[h][jj] = ev[it] * inv;
        }
    }
    __syncthreads();

    {
        int h = t >> 5;
        float2 acc = make_float2(0.f, 0.f);
        const float* wrow = w_sh[h];
        #pragma unroll 4
        for (int jj = 0; jj < deg; jj++) {
            float w = wrow[jj];
            float2 v = *(const float2*)&g_h[(size_t)nbr_sh[jj] * HD + 2 * t];
            acc.x += w * v.x;
            acc.y += w * v.y;
        }
        float2 r;
        r.x = (acc.x > 0.f) ? acc.x : expm1f(acc.x);
        r.y = (acc.y > 0.f) ? acc.y : expm1f(acc.y);
        *(float2*)&g_x2[(size_t)i * HD + 2 * t] = r;
    }
}

// --------- launch 3: GEMM2 (32-row tiles) + flags + layer-2 attention --------
__global__ __launch_bounds__(256) void k_fused2(
    const float* __restrict__ W2,
    const float* __restrict__ a2_src, const float* __restrict__ a2_dst,
    float* __restrict__ out)
{
    extern __shared__ float sm[];
    const unsigned FULL = 0xffffffffu;
    int b = blockIdx.x;
    int t = threadIdx.x, lane = t & 31, w = t >> 5;

    // phase A: h2p rows [32b, 32b+32), fused s2i/s2j
    gemm_tile<32, 10, Cc>(g_x2, W2, g_h2p, C2, b * 32, 0,
                          a2_src, a2_dst, g_s2i, g_s2j, sm);
    __threadfence();
    __syncthreads();
    if (t == 0) atomicExch(&g_flag2[b], 1);

    // phase B: layer-2 for this block's 32 nodes; 1 warp per node, 4 nodes/warp
    for (int q = 0; q < 4; q++) {
        int i = b * 32 + w * 4 + q;
        int deg = g_deg[i];
        float sii = g_s2i[i];
        int idx[4]; float ev[4];
        float m = -1e30f;
        #pragma unroll
        for (int c4 = 0; c4 < 4; c4++) {
            int jj = c4 * 32 + lane;
            int j = 0;
            float e = -1e30f;
            if (jj < deg) {
                j = g_nbr[i * MAXDEG + jj];
                volatile int* fl = &g_flag2[j >> 5];
                while (*fl == 0) __nanosleep(40);
                float xx = sii + g_s2j[j];
                e = (xx >= 0.f) ? xx : 0.2f * xx;
            }
            idx[c4] = j;
            ev[c4] = e;
            m = fmaxf(m, e);
        }
        #pragma unroll
        for (int o = 16; o; o >>= 1) m = fmaxf(m, __shfl_xor_sync(FULL, m, o));
        float s = 0.f;
        #pragma unroll
        for (int c4 = 0; c4 < 4; c4++) {
            int jj = c4 * 32 + lane;
            float wv = (jj < deg) ? expf(ev[c4] - m) : 0.f;
            ev[c4] = wv;
            s += wv;
        }
        #pragma unroll
        for (int o = 16; o; o >>= 1) s += __shfl_xor_sync(FULL, s, o);
        float inv = 1.f / s;
        #pragma unroll
        for (int c4 = 0; c4 < 4; c4++) ev[c4] *= inv;

        float a0 = 0.f, a1 = 0.f;
        for (int jj = 0; jj < deg; jj++) {
            int cq = jj >> 5, l = jj & 31;
            float wgt;
            int j;
            if (cq == 0)      { wgt = __shfl_sync(FULL, ev[0], l); j = __shfl_sync(FULL, idx[0], l); }
            else if (cq == 1) { wgt = __shfl_sync(FULL, ev[1], l); j = __shfl_sync(FULL, idx[1], l); }
            else if (cq == 2) { wgt = __shfl_sync(FULL, ev[2], l); j = __shfl_sync(FULL, idx[2], l); }
            else              { wgt = __shfl_sync(FULL, ev[3], l); j = __shfl_sync(FULL, idx[3], l); }
            a0 += wgt * g_h2p[(size_t)j * C2 + lane];
            if (lane < Cc - 32) a1 += wgt * g_h2p[(size_t)j * C2 + 32 + lane];
        }
        out[(size_t)i * Cc + lane] = a0;
        if (lane < Cc - 32) out[(size_t)i * Cc + 32 + lane] = a1;
    }
}

// ---------------- launch -----------------------------------------------------
#define SMEM_F1 ((2 * 64 * 36 + 2 * 32 * 72 + 8 * 64) * 4)   // 38912
#define SMEM_F2 ((2 * 32 * 36 + 2 * 32 * 72 + 8 * 32) * 4)   // 28672

extern "C" void kernel_launch(void* const* d_in, const int* in_sizes, int n_in,
                              void* d_out, int out_size) {
    const float*         x      = (const float*)d_in[0];
    const unsigned char* adj    = (const unsigned char*)d_in[1];
    const float*         W1     = (const float*)d_in[2];
    const float*         a1_src = (const float*)d_in[3];
    const float*         a1_dst = (const float*)d_in[4];
    const float*         W2     = (const float*)d_in[5];
    const float*         a2_src = (const float*)d_in[6];
    const float*         a2_dst = (const float*)d_in[7];
    float* out = (float*)d_out;

    k_fused1<<<1024, 256, SMEM_F1>>>(x, adj, W1, a1_src, a1_dst);
    k_layer1<<<Nn, 256>>>();
    k_fused2<<<128, 256, SMEM_F2>>>(W2, a2_src, a2_dst, out);
}